// round 7
// baseline (speedup 1.0000x reference)
#include <cuda_runtime.h>
#include <cuda_bf16.h>
#include <cstdint>
#include <math.h>

// Problem dims
#define BATCH 2048
#define HDIM  512
#define TSTEP 128
#define VDIM  64
#define GDIM  2048   // 4*HDIM

// ---------------- scratch (device globals; no allocation allowed) ----------
__device__ float g_xg[BATCH * GDIM];                         // 16 MB  x_gates
__device__ float g_c[BATCH * HDIM];                          // 4 MB   cell state
__device__ float g_hs[(size_t)BATCH * TSTEP * HDIM];         // 512 MB hidden states (fp32)
// h as int8 digit pair, double buffered by t parity: h = a1/64 + a2/8192
__device__ signed char g_hA1[2][BATCH * HDIM];
__device__ signed char g_hA2[2][BATCH * HDIM];
// w_hh digits rearranged per N-block (by in 0..31):
// [32][64 rows][512 k], tile row r -> orig w row (r>>4)*512 + by*16 + (r&15)
// w = b1/2048 + b2/262144
__device__ signed char g_wB1[32][64 * HDIM];
__device__ signed char g_wB2[32][64 * HDIM];

// digit combine scales
#define S1 (1.0f / 131072.0f)     // 2^-17  (a1*b1)
#define S2 (1.0f / 16777216.0f)   // 2^-24  (a1*b2 + a2*b1)

// ---------------- packed f32x2 helpers (FFMA2 path) -------------------------
typedef unsigned long long ull;

__device__ __forceinline__ ull ffma2(ull a, ull b, ull c) {
    ull d;
    asm("fma.rn.f32x2 %0, %1, %2, %3;" : "=l"(d) : "l"(a), "l"(b), "l"(c));
    return d;
}
__device__ __forceinline__ ull pk2(float x, float y) {
    ull r;
    asm("mov.b64 %0, {%1, %2};" : "=l"(r) : "f"(x), "f"(y));
    return r;
}
__device__ __forceinline__ float2 up2(ull v) {
    float2 r;
    asm("mov.b64 {%0, %1}, %2;" : "=f"(r.x), "=f"(r.y) : "l"(v));
    return r;
}

__device__ __forceinline__ float sigm(float x) {
    return 1.0f / (1.0f + __expf(-x));
}
__device__ __forceinline__ float tanh_fast(float x) {
    float e = __expf(-2.0f * fabsf(x));
    float r = (1.0f - e) / (1.0f + e);
    return copysignf(r, x);
}

// ---------------- mma.sync / ldmatrix / cp.async helpers --------------------
__device__ __forceinline__ uint32_t smem_u32(const void* p) {
    uint32_t a;
    asm("{ .reg .u64 t; cvta.to.shared.u64 t, %1; cvt.u32.u64 %0, t; }" : "=r"(a) : "l"(p));
    return a;
}
__device__ __forceinline__ void ldsm_x4(uint32_t* r, uint32_t addr) {
    asm volatile("ldmatrix.sync.aligned.m8n8.x4.shared.b16 {%0,%1,%2,%3}, [%4];"
                 : "=r"(r[0]), "=r"(r[1]), "=r"(r[2]), "=r"(r[3]) : "r"(addr));
}
// s8 MMA m16n8k32, s32 accum
__device__ __forceinline__ void mma_s8(int* d, const uint32_t* a, const uint32_t* b) {
    asm volatile("mma.sync.aligned.m16n8k32.row.col.s32.s8.s8.s32 "
                 "{%0,%1,%2,%3}, {%4,%5,%6,%7}, {%8,%9}, {%0,%1,%2,%3};"
                 : "+r"(d[0]), "+r"(d[1]), "+r"(d[2]), "+r"(d[3])
                 : "r"(a[0]), "r"(a[1]), "r"(a[2]), "r"(a[3]), "r"(b[0]), "r"(b[1]));
}
__device__ __forceinline__ void cpa16(uint32_t dst, const void* src) {
    asm volatile("cp.async.cg.shared.global [%0], [%1], 16;"
                 :: "r"(dst), "l"(__cvta_generic_to_global(src)) : "memory");
}
#define CPA_COMMIT() asm volatile("cp.async.commit_group;" ::: "memory")
#define CPA_WAIT0()  asm volatile("cp.async.wait_group 0;" ::: "memory")
#define CPA_WAIT1()  asm volatile("cp.async.wait_group 1;" ::: "memory")

// ---------------- init: zero c and h0 digits ---------------------------------
__global__ void init_kernel() {
    int i = blockIdx.x * blockDim.x + threadIdx.x;
    if (i < BATCH * HDIM) {
        g_c[i] = 0.0f;
        g_hA1[0][i] = 0;
        g_hA2[0][i] = 0;
    }
}

// ---------------- wprep: digit-decompose + rearrange w_hh --------------------
__global__ void wprep_kernel(const float* __restrict__ w_hh) {
    int i = blockIdx.x * blockDim.x + threadIdx.x;   // over 32*64*512
    if (i >= 32 * 64 * HDIM) return;
    int k = i & (HDIM - 1);
    int r = (i >> 9) & 63;
    int by = i >> 15;
    int orig_row = ((r >> 4) << 9) + by * 16 + (r & 15);
    float w = w_hh[(size_t)orig_row * HDIM + k];
    float b1 = rintf(w * 2048.0f);                   // |w| <= 1/sqrt(512) -> |b1| <= 91
    float rem = w - b1 * (1.0f / 2048.0f);
    float b2 = rintf(rem * 262144.0f);               // |b2| <= 64
    g_wB1[by][r * HDIM + k] = (signed char)(int)b1;
    g_wB2[by][r * HDIM + k] = (signed char)(int)b2;
}

// -------- pre: x_gates = z @ w_ih.T + b_ih + b_hh (FFMA2, one-time) ----------
__global__ __launch_bounds__(256, 2)
void pre_kernel(const float* __restrict__ z,
                const float* __restrict__ w_ih,
                const float* __restrict__ b_ih,
                const float* __restrict__ b_hh) {
    __shared__ float As[16][132];
    __shared__ float Bs[16][130];

    const int bm = blockIdx.x;
    const int j0 = blockIdx.y * 32;
    const int tid = threadIdx.x;
    const int tr = tid >> 4, tc = tid & 15;
    const int jj0 = tc * 2;

    ull acc[8][4];
#pragma unroll
    for (int i = 0; i < 8; i++)
#pragma unroll
        for (int g = 0; g < 4; g++) acc[i][g] = 0ull;

    for (int k0 = 0; k0 < HDIM; k0 += 16) {
#pragma unroll
        for (int it = 0; it < 2; it++) {
            int i = tid + it * 256;
            int row = i >> 2, kq = (i & 3) * 4;
            float4 va = *(const float4*)(z + (size_t)(bm * 128 + row) * HDIM + k0 + kq);
            As[kq + 0][row] = va.x; As[kq + 1][row] = va.y;
            As[kq + 2][row] = va.z; As[kq + 3][row] = va.w;
            int n = row;
            int gcol = ((n >> 5) << 9) + j0 + (n & 31);
            float4 vb = *(const float4*)(w_ih + (size_t)gcol * HDIM + k0 + kq);
            Bs[kq + 0][n] = vb.x; Bs[kq + 1][n] = vb.y;
            Bs[kq + 2][n] = vb.z; Bs[kq + 3][n] = vb.w;
        }
        __syncthreads();
#pragma unroll
        for (int kk = 0; kk < 16; kk++) {
            float4 a0 = *(const float4*)&As[kk][tr * 8];
            float4 a1 = *(const float4*)&As[kk][tr * 8 + 4];
            ull b0 = *(const ull*)&Bs[kk][jj0];
            ull b1 = *(const ull*)&Bs[kk][32 + jj0];
            ull b2 = *(const ull*)&Bs[kk][64 + jj0];
            ull b3 = *(const ull*)&Bs[kk][96 + jj0];
            float av[8] = {a0.x, a0.y, a0.z, a0.w, a1.x, a1.y, a1.z, a1.w};
#pragma unroll
            for (int i = 0; i < 8; i++) {
                ull ad = pk2(av[i], av[i]);
                acc[i][0] = ffma2(ad, b0, acc[i][0]);
                acc[i][1] = ffma2(ad, b1, acc[i][1]);
                acc[i][2] = ffma2(ad, b2, acc[i][2]);
                acc[i][3] = ffma2(ad, b3, acc[i][3]);
            }
        }
        __syncthreads();
    }

    const int b0r = bm * 128 + tr * 8;
#pragma unroll
    for (int i = 0; i < 8; i++) {
        int b = b0r + i;
        float2 vv[4];
#pragma unroll
        for (int g = 0; g < 4; g++) vv[g] = up2(acc[i][g]);
#pragma unroll
        for (int g = 0; g < 4; g++) {
            int c0 = g * 512 + j0 + jj0;
            g_xg[(size_t)b * GDIM + c0]     = vv[g].x + b_ih[c0]     + b_hh[c0];
            g_xg[(size_t)b * GDIM + c0 + 1] = vv[g].y + b_ih[c0 + 1] + b_hh[c0 + 1];
        }
    }
}

// ============================================================================
// step_mma: gates = x_gates + h@w_hh.T via s8 mma (3 digit products)
//   grid (16, 32), 256 threads (8 warps), 2 CTAs/SM.
//   CTA tile M=128 x N=64 (n = g*16 + hcol), warp tile M32 x N32.
//   K=512 bytes in 8 chunks of 64, cp.async TRIPLE buffer.
// ============================================================================
#define A1_OFF 0
#define A2_OFF 8192
#define B1_OFF 16384
#define B2_OFF 20480
#define BUFSZ  24576
#define NBUF   3
#define EPI_STRIDE 66
#define SMEM_TOTAL (NBUF * BUFSZ)   // 73728 >= epi 128*66*4 = 33792

__global__ __launch_bounds__(256, 2)
void step_mma(int t) {
    extern __shared__ char smem[];
    const uint32_t smem_base = smem_u32(smem);
    float* E = (float*)smem;

    const int tid = threadIdx.x;
    const int wid = tid >> 5;
    const int lid = tid & 31;
    const int bm = blockIdx.x;
    const int by = blockIdx.y;

    const signed char* __restrict__ hin1 = g_hA1[t & 1];
    const signed char* __restrict__ hin2 = g_hA2[t & 1];
    signed char* __restrict__ hout1 = g_hA1[(t & 1) ^ 1];
    signed char* __restrict__ hout2 = g_hA2[(t & 1) ^ 1];
    const signed char* __restrict__ wb1 = g_wB1[by];
    const signed char* __restrict__ wb2 = g_wB2[by];

    // ---- cp.async addressing ----
    // A digits: 128 rows x 4 units (16B), 512 units -> 2 per thread per digit
    const int ar0 = tid >> 2, au = tid & 3;
    const int ar1 = ((tid + 256) >> 2);
    const uint32_t dA0 = smem_base + ar0 * 64 + ((au ^ (ar0 & 3)) * 16);
    const uint32_t dA1 = smem_base + ar1 * 64 + ((au ^ (ar1 & 3)) * 16);
    const size_t sA0 = (size_t)(bm * 128 + ar0) * HDIM + au * 16;
    const size_t sA1 = (size_t)(bm * 128 + ar1) * HDIM + au * 16;
    // B digits: 64 rows x 4 units, 256 units -> 1 per thread per digit
    const int br = tid >> 2, bu = tid & 3;
    const uint32_t dB = smem_base + br * 64 + ((bu ^ (br & 3)) * 16);
    const size_t sB = (size_t)br * HDIM + bu * 16;

    // ---- ldmatrix lane address offsets (kstep 0; kstep 1 -> XOR 32) ----
    const int warp_m = wid >> 1;           // 0..3 -> m base warp_m*32
    const int warp_n = wid & 1;            // 0..1 -> n base warp_n*32
    uint32_t a_off[2], b_off[2];
    {
        // A (m16k32 frags): lanes 0-7 rows ra..+7 kbytes 0-15; 8-15 rows +8;
        //                   16-23 rows ra..+7 kbytes 16-31; 24-31 rows +8 k16-31
        int ra = warp_m * 32 + (lid & 7) + (((lid >> 3) & 1) << 3);
        int ua = (lid >> 4) & 1;
#pragma unroll
        for (int i = 0; i < 2; i++) {
            int row = ra + i * 16;
            a_off[i] = row * 64 + ((ua ^ (row & 3)) * 16);
        }
        // B (n8k32 frags, 2 n8-tiles per ldsm): lanes 0-7 n-rows rb..+7 k0-15;
        //   8-15 same rows k16-31; 16-23 rows +8 k0-15; 24-31 rows +8 k16-31
        int rb = warp_n * 32 + (lid & 7) + (((lid >> 4) & 1) << 3);
        int ub = (lid >> 3) & 1;
#pragma unroll
        for (int q = 0; q < 2; q++) {
            int row = rb + q * 16;
            b_off[q] = row * 64 + ((ub ^ (row & 3)) * 16);
        }
    }

    int acc1[2][4][4], acc2[2][4][4];
#pragma unroll
    for (int i = 0; i < 2; i++)
#pragma unroll
        for (int f = 0; f < 4; f++)
#pragma unroll
            for (int v = 0; v < 4; v++) { acc1[i][f][v] = 0; acc2[i][f][v] = 0; }

    // ---- prologue: issue chunks 0 and 1 ----
#pragma unroll
    for (int c = 0; c < 2; c++) {
        const uint32_t bo = c * BUFSZ;
        const size_t ko = (size_t)c * 64;
        cpa16(dA0 + bo + A1_OFF, hin1 + sA0 + ko);
        cpa16(dA1 + bo + A1_OFF, hin1 + sA1 + ko);
        cpa16(dA0 + bo + A2_OFF, hin2 + sA0 + ko);
        cpa16(dA1 + bo + A2_OFF, hin2 + sA1 + ko);
        cpa16(dB + bo + B1_OFF, wb1 + sB + ko);
        cpa16(dB + bo + B2_OFF, wb2 + sB + ko);
        CPA_COMMIT();
    }
    CPA_WAIT1();
    __syncthreads();

    int buf = 0;
    for (int c = 0; c < 8; c++) {
        if (c <= 5) {
            const uint32_t bo = ((c + 2) % NBUF) * BUFSZ;
            const size_t ko = (size_t)(c + 2) * 64;
            cpa16(dA0 + bo + A1_OFF, hin1 + sA0 + ko);
            cpa16(dA1 + bo + A1_OFF, hin1 + sA1 + ko);
            cpa16(dA0 + bo + A2_OFF, hin2 + sA0 + ko);
            cpa16(dA1 + bo + A2_OFF, hin2 + sA1 + ko);
            cpa16(dB + bo + B1_OFF, wb1 + sB + ko);
            cpa16(dB + bo + B2_OFF, wb2 + sB + ko);
            CPA_COMMIT();
        }

        const uint32_t base = smem_base + buf * BUFSZ;
#pragma unroll
        for (int s = 0; s < 2; s++) {
            const uint32_t sx = s ? 32u : 0u;
            uint32_t a1f[2][4], a2f[2][4], b1f[2][4], b2f[2][4];
            // digit product 1: a1*b1 -> acc1
#pragma unroll
            for (int i = 0; i < 2; i++) ldsm_x4(a1f[i], base + A1_OFF + (a_off[i] ^ sx));
#pragma unroll
            for (int q = 0; q < 2; q++) ldsm_x4(b1f[q], base + B1_OFF + (b_off[q] ^ sx));
#pragma unroll
            for (int i = 0; i < 2; i++)
#pragma unroll
                for (int f = 0; f < 4; f++)
                    mma_s8(acc1[i][f], a1f[i], &b1f[f >> 1][(f & 1) * 2]);
            // digit product 2: a1*b2 -> acc2
#pragma unroll
            for (int q = 0; q < 2; q++) ldsm_x4(b2f[q], base + B2_OFF + (b_off[q] ^ sx));
#pragma unroll
            for (int i = 0; i < 2; i++)
#pragma unroll
                for (int f = 0; f < 4; f++)
                    mma_s8(acc2[i][f], a1f[i], &b2f[f >> 1][(f & 1) * 2]);
            // digit product 3: a2*b1 -> acc2
#pragma unroll
            for (int i = 0; i < 2; i++) ldsm_x4(a2f[i], base + A2_OFF + (a_off[i] ^ sx));
#pragma unroll
            for (int i = 0; i < 2; i++)
#pragma unroll
                for (int f = 0; f < 4; f++)
                    mma_s8(acc2[i][f], a2f[i], &b1f[f >> 1][(f & 1) * 2]);
        }

        if (c <= 5) {
            CPA_WAIT1();
            __syncthreads();
        } else if (c == 6) {
            CPA_WAIT0();
            __syncthreads();
        }
        buf = (buf + 1 == NBUF) ? 0 : buf + 1;
    }

    // ---- combine digit accumulators, stage to smem ----
    __syncthreads();
    {
        const int rr = warp_m * 32 + (lid >> 2);
        const int c0 = warp_n * 32 + (lid & 3) * 2;
#pragma unroll
        for (int i = 0; i < 2; i++)
#pragma unroll
            for (int f = 0; f < 4; f++) {
                int r = rr + i * 16;
                int cc = c0 + f * 8;
                float v0 = (float)acc1[i][f][0] * S1 + (float)acc2[i][f][0] * S2;
                float v1 = (float)acc1[i][f][1] * S1 + (float)acc2[i][f][1] * S2;
                float v2 = (float)acc1[i][f][2] * S1 + (float)acc2[i][f][2] * S2;
                float v3 = (float)acc1[i][f][3] * S1 + (float)acc2[i][f][3] * S2;
                *(float2*)&E[r * EPI_STRIDE + cc]       = make_float2(v0, v1);
                *(float2*)&E[(r + 8) * EPI_STRIDE + cc] = make_float2(v2, v3);
            }
    }
    __syncthreads();

    // ---- fused LSTM cell epilogue (16 hcols x 128 rows) ----
    {
        const int hl = tid & 15;
        const int mb = (tid >> 4) * 8;
        const int hcol_g = by * 16 + hl;
#pragma unroll 4
        for (int j = 0; j < 8; j++) {
            const int m = mb + j;
            const int b = bm * 128 + m;
            const float* xg = g_xg + (size_t)b * GDIM + hcol_g;
            float gi = E[m * EPI_STRIDE + hl]      + xg[0];
            float gf = E[m * EPI_STRIDE + 16 + hl] + xg[512];
            float gg = E[m * EPI_STRIDE + 32 + hl] + xg[1024];
            float go = E[m * EPI_STRIDE + 48 + hl] + xg[1536];
            const size_t ci = (size_t)b * HDIM + hcol_g;
            float cn = sigm(gf) * g_c[ci] + sigm(gi) * tanh_fast(gg);
            g_c[ci] = cn;
            float hn = sigm(go) * tanh_fast(cn);
            g_hs[((size_t)b * TSTEP + t) * HDIM + hcol_g] = hn;
            // int8 digits: hn = a1/64 + a2/8192 + eps(2^-14)
            float a1 = rintf(hn * 64.0f);
            float a2 = rintf((hn - a1 * (1.0f / 64.0f)) * 8192.0f);
            hout1[ci] = (signed char)(int)a1;
            hout2[ci] = (signed char)(int)a2;
        }
    }
}

// -------- fc: out = relu(hs @ fc_w.T + fc_b) --------------------------------
__global__ __launch_bounds__(256)
void fc_kernel(const float* __restrict__ fc_w,
               const float* __restrict__ fc_b,
               float* __restrict__ out) {
    __shared__ float hsS[16][514];
    const size_t row0 = (size_t)blockIdx.x * 16;
    const int tid = threadIdx.x;

#pragma unroll
    for (int it = 0; it < 16; it++) {
        int i = tid + it * 256;
        int row = i >> 8;
        int cc = (i & 255) * 2;
        float2 v = *(const float2*)(g_hs + (row0 + row) * HDIM + cc);
        *(float2*)&hsS[row][cc] = v;
    }
    __syncthreads();

    const int r = tid & 15;
    const int v0 = (tid >> 4) * 4;
    ull acc[4] = {0ull, 0ull, 0ull, 0ull};
    const float* w0 = fc_w + (size_t)v0 * HDIM;

#pragma unroll 8
    for (int k = 0; k < HDIM; k += 2) {
        ull a = *(const ull*)&hsS[r][k];
        acc[0] = ffma2(a, *(const ull*)(w0 + k),        acc[0]);
        acc[1] = ffma2(a, *(const ull*)(w0 + 512 + k),  acc[1]);
        acc[2] = ffma2(a, *(const ull*)(w0 + 1024 + k), acc[2]);
        acc[3] = ffma2(a, *(const ull*)(w0 + 1536 + k), acc[3]);
    }
#pragma unroll
    for (int j = 0; j < 4; j++) {
        float2 s = up2(acc[j]);
        float v = s.x + s.y + fc_b[v0 + j];
        out[(row0 + r) * VDIM + v0 + j] = fmaxf(v, 0.0f);
    }
}

// ---------------- launch ----------------------------------------------------
extern "C" void kernel_launch(void* const* d_in, const int* in_sizes, int n_in,
                              void* d_out, int out_size) {
    const float* z    = (const float*)d_in[0];
    const float* w_ih = (const float*)d_in[1];
    const float* w_hh = (const float*)d_in[2];
    const float* b_ih = (const float*)d_in[3];
    const float* b_hh = (const float*)d_in[4];
    const float* fc_w = (const float*)d_in[5];
    const float* fc_b = (const float*)d_in[6];
    float* out = (float*)d_out;

    cudaFuncSetAttribute(step_mma, cudaFuncAttributeMaxDynamicSharedMemorySize, SMEM_TOTAL);

    init_kernel<<<(BATCH * HDIM + 255) / 256, 256>>>();
    wprep_kernel<<<(32 * 64 * HDIM + 255) / 256, 256>>>(w_hh);
    pre_kernel<<<dim3(16, 16), 256>>>(z, w_ih, b_ih, b_hh);
    for (int t = 0; t < TSTEP; t++) {
        step_mma<<<dim3(16, 32), 256, SMEM_TOTAL>>>(t);
    }
    fc_kernel<<<(BATCH * TSTEP) / 16, 256>>>(fc_w, fc_b, out);
}

// round 8
// speedup vs baseline: 1.7824x; 1.7824x over previous
#include <cuda_runtime.h>
#include <cuda_bf16.h>
#include <cstdint>
#include <math.h>

// Problem dims
#define BATCH 2048
#define HDIM  512
#define TSTEP 128
#define VDIM  64
#define GDIM  2048   // 4*HDIM

// ---------------- scratch (device globals; no allocation allowed) ----------
__device__ float g_xg[BATCH * GDIM];                         // 16 MB  x_gates
__device__ float g_c[BATCH * HDIM];                          // 4 MB   cell state
__device__ float g_hs[(size_t)BATCH * TSTEP * HDIM];         // 512 MB hidden states (fp32)
// h as bf16 split, double buffered by t parity
__device__ __nv_bfloat16 g_hAhi[2][BATCH * HDIM];
__device__ __nv_bfloat16 g_hAlo[2][BATCH * HDIM];
// w_hh rearranged per N-block (by in 0..31): [32][64 rows][512 k],
// tile row r -> orig row (r>>4)*512 + by*16 + (r&15)   (gate-major within block)
__device__ __nv_bfloat16 g_wBhi[32][64 * HDIM];
__device__ __nv_bfloat16 g_wBlo[32][64 * HDIM];

// ---------------- packed f32x2 helpers (FFMA2 path) -------------------------
typedef unsigned long long ull;

__device__ __forceinline__ ull ffma2(ull a, ull b, ull c) {
    ull d;
    asm("fma.rn.f32x2 %0, %1, %2, %3;" : "=l"(d) : "l"(a), "l"(b), "l"(c));
    return d;
}
__device__ __forceinline__ ull pk2(float x, float y) {
    ull r;
    asm("mov.b64 %0, {%1, %2};" : "=l"(r) : "f"(x), "f"(y));
    return r;
}
__device__ __forceinline__ float2 up2(ull v) {
    float2 r;
    asm("mov.b64 {%0, %1}, %2;" : "=f"(r.x), "=f"(r.y) : "l"(v));
    return r;
}

__device__ __forceinline__ float sigm(float x) {
    return 1.0f / (1.0f + __expf(-x));
}
__device__ __forceinline__ float tanh_fast(float x) {
    float e = __expf(-2.0f * fabsf(x));
    float r = (1.0f - e) / (1.0f + e);
    return copysignf(r, x);
}

// ---------------- mma.sync / ldmatrix / cp.async helpers --------------------
__device__ __forceinline__ uint32_t smem_u32(const void* p) {
    uint32_t a;
    asm("{ .reg .u64 t; cvta.to.shared.u64 t, %1; cvt.u32.u64 %0, t; }" : "=r"(a) : "l"(p));
    return a;
}
__device__ __forceinline__ void ldsm_x4(uint32_t* r, uint32_t addr) {
    asm volatile("ldmatrix.sync.aligned.m8n8.x4.shared.b16 {%0,%1,%2,%3}, [%4];"
                 : "=r"(r[0]), "=r"(r[1]), "=r"(r[2]), "=r"(r[3]) : "r"(addr));
}
__device__ __forceinline__ void mma16816(float* d, const uint32_t* a, const uint32_t* b) {
    asm volatile("mma.sync.aligned.m16n8k16.row.col.f32.bf16.bf16.f32 "
                 "{%0,%1,%2,%3}, {%4,%5,%6,%7}, {%8,%9}, {%0,%1,%2,%3};"
                 : "+f"(d[0]), "+f"(d[1]), "+f"(d[2]), "+f"(d[3])
                 : "r"(a[0]), "r"(a[1]), "r"(a[2]), "r"(a[3]), "r"(b[0]), "r"(b[1]));
}
__device__ __forceinline__ void cpa16(uint32_t dst, const void* src) {
    asm volatile("cp.async.cg.shared.global [%0], [%1], 16;"
                 :: "r"(dst), "l"(__cvta_generic_to_global(src)) : "memory");
}
#define CPA_COMMIT() asm volatile("cp.async.commit_group;" ::: "memory")
#define CPA_WAIT0()  asm volatile("cp.async.wait_group 0;" ::: "memory")
#define CPA_WAIT1()  asm volatile("cp.async.wait_group 1;" ::: "memory")

// ---------------- init: zero c and h0 splits ---------------------------------
__global__ void init_kernel() {
    int i = blockIdx.x * blockDim.x + threadIdx.x;
    if (i < BATCH * HDIM) {
        g_c[i] = 0.0f;
        g_hAhi[0][i] = __float2bfloat16(0.0f);
        g_hAlo[0][i] = __float2bfloat16(0.0f);
    }
}

// ---------------- wprep: decompose + rearrange w_hh --------------------------
__global__ void wprep_kernel(const float* __restrict__ w_hh) {
    int i = blockIdx.x * blockDim.x + threadIdx.x;   // over 32*64*512
    if (i >= 32 * 64 * HDIM) return;
    int k = i & (HDIM - 1);
    int r = (i >> 9) & 63;
    int by = i >> 15;
    int orig_row = ((r >> 4) << 9) + by * 16 + (r & 15);
    float w = w_hh[(size_t)orig_row * HDIM + k];
    __nv_bfloat16 hi = __float2bfloat16_rn(w);
    float rem = w - __bfloat162float(hi);
    g_wBhi[by][r * HDIM + k] = hi;
    g_wBlo[by][r * HDIM + k] = __float2bfloat16_rn(rem);
}

// -------- pre: x_gates = z @ w_ih.T + b_ih + b_hh (FFMA2, one-time) ----------
__global__ __launch_bounds__(256, 2)
void pre_kernel(const float* __restrict__ z,
                const float* __restrict__ w_ih,
                const float* __restrict__ b_ih,
                const float* __restrict__ b_hh) {
    __shared__ float As[16][132];
    __shared__ float Bs[16][130];

    const int bm = blockIdx.x;
    const int j0 = blockIdx.y * 32;
    const int tid = threadIdx.x;
    const int tr = tid >> 4, tc = tid & 15;
    const int jj0 = tc * 2;

    ull acc[8][4];
#pragma unroll
    for (int i = 0; i < 8; i++)
#pragma unroll
        for (int g = 0; g < 4; g++) acc[i][g] = 0ull;

    for (int k0 = 0; k0 < HDIM; k0 += 16) {
#pragma unroll
        for (int it = 0; it < 2; it++) {
            int i = tid + it * 256;
            int row = i >> 2, kq = (i & 3) * 4;
            float4 va = *(const float4*)(z + (size_t)(bm * 128 + row) * HDIM + k0 + kq);
            As[kq + 0][row] = va.x; As[kq + 1][row] = va.y;
            As[kq + 2][row] = va.z; As[kq + 3][row] = va.w;
            int n = row;
            int gcol = ((n >> 5) << 9) + j0 + (n & 31);
            float4 vb = *(const float4*)(w_ih + (size_t)gcol * HDIM + k0 + kq);
            Bs[kq + 0][n] = vb.x; Bs[kq + 1][n] = vb.y;
            Bs[kq + 2][n] = vb.z; Bs[kq + 3][n] = vb.w;
        }
        __syncthreads();
#pragma unroll
        for (int kk = 0; kk < 16; kk++) {
            float4 a0 = *(const float4*)&As[kk][tr * 8];
            float4 a1 = *(const float4*)&As[kk][tr * 8 + 4];
            ull b0 = *(const ull*)&Bs[kk][jj0];
            ull b1 = *(const ull*)&Bs[kk][32 + jj0];
            ull b2 = *(const ull*)&Bs[kk][64 + jj0];
            ull b3 = *(const ull*)&Bs[kk][96 + jj0];
            float av[8] = {a0.x, a0.y, a0.z, a0.w, a1.x, a1.y, a1.z, a1.w};
#pragma unroll
            for (int i = 0; i < 8; i++) {
                ull ad = pk2(av[i], av[i]);
                acc[i][0] = ffma2(ad, b0, acc[i][0]);
                acc[i][1] = ffma2(ad, b1, acc[i][1]);
                acc[i][2] = ffma2(ad, b2, acc[i][2]);
                acc[i][3] = ffma2(ad, b3, acc[i][3]);
            }
        }
        __syncthreads();
    }

    const int b0r = bm * 128 + tr * 8;
#pragma unroll
    for (int i = 0; i < 8; i++) {
        int b = b0r + i;
        float2 vv[4];
#pragma unroll
        for (int g = 0; g < 4; g++) vv[g] = up2(acc[i][g]);
#pragma unroll
        for (int g = 0; g < 4; g++) {
            int c0 = g * 512 + j0 + jj0;
            g_xg[(size_t)b * GDIM + c0]     = vv[g].x + b_ih[c0]     + b_hh[c0];
            g_xg[(size_t)b * GDIM + c0 + 1] = vv[g].y + b_ih[c0 + 1] + b_hh[c0 + 1];
        }
    }
}

// ============================================================================
// step_mma: gates = x_gates + h@w_hh.T via mma.sync bf16 3-pass split
//   grid (16, 32), 256 threads (8 warps), 3 CTAs/SM (forced by launch_bounds).
//   CTA tile M=128 x N=64 (n = g*16 + hcol), warp tile M32 x N32.
//   K=512 in 16 chunks of 32 elems, cp.async TRIPLE buffer.
// ============================================================================
#define KCH 32
#define AH_OFF 0
#define AL_OFF 8192
#define BH_OFF 16384
#define BL_OFF 20480
#define BUFSZ  24576
#define NBUF   3
#define EPI_STRIDE 66
#define SMEM_TOTAL (NBUF * BUFSZ)   // 73728 >= epi 128*66*4 = 33792

__global__ __launch_bounds__(256, 3)
void step_mma(int t) {
    extern __shared__ char smem[];
    const uint32_t smem_base = smem_u32(smem);
    float* E = (float*)smem;

    const int tid = threadIdx.x;
    const int wid = tid >> 5;
    const int lid = tid & 31;
    const int bm = blockIdx.x;
    const int by = blockIdx.y;

    const __nv_bfloat16* __restrict__ hin_hi = g_hAhi[t & 1];
    const __nv_bfloat16* __restrict__ hin_lo = g_hAlo[t & 1];
    __nv_bfloat16* __restrict__ hout_hi = g_hAhi[(t & 1) ^ 1];
    __nv_bfloat16* __restrict__ hout_lo = g_hAlo[(t & 1) ^ 1];
    const __nv_bfloat16* __restrict__ wb_hi = g_wBhi[by];
    const __nv_bfloat16* __restrict__ wb_lo = g_wBlo[by];

    // ---- cp.async addressing (offsets in elements, fit 32-bit) ----
    // A tiles: 128 rows x 4 16B-units; 512 units -> 2/thread/digit
    const int ar0 = tid >> 2, au = tid & 3;
    const int ar1 = ar0 + 64;
    const uint32_t dA0 = smem_base + ar0 * 64 + ((au ^ (ar0 & 3)) * 16);
    const uint32_t dA1 = smem_base + ar1 * 64 + ((au ^ (ar1 & 3)) * 16);
    const uint32_t sA0 = (uint32_t)(bm * 128 + ar0) * HDIM + au * 8;
    const uint32_t sA1 = (uint32_t)(bm * 128 + ar1) * HDIM + au * 8;
    // B tiles: 64 rows x 4 units; 256 units -> 1/thread/digit
    const int br = tid >> 2, bu = tid & 3;
    const uint32_t dB = smem_base + br * 64 + ((bu ^ (br & 3)) * 16);
    const uint32_t sB = (uint32_t)br * HDIM + bu * 8;

    // ---- ldmatrix lane address offsets (k-step s=0; s=1 -> XOR 32) ----
    const int warp_m = wid >> 1;           // 0..3 -> m base warp_m*32
    const int warp_n = wid & 1;            // 0..1 -> n base warp_n*32
    uint32_t a_off[2], b_off[2];
    {
        int j = lid >> 3;
        int ra = warp_m * 32 + (lid & 7) + ((j & 1) << 3);
        int kh = j >> 1;
#pragma unroll
        for (int i = 0; i < 2; i++) {
            int row = ra + i * 16;
            a_off[i] = row * 64 + ((kh ^ (row & 3)) * 16);
        }
        int rb = warp_n * 32 + (lid & 7) + ((j >> 1) << 3);
        int bkh = j & 1;
#pragma unroll
        for (int q = 0; q < 2; q++) {
            int row = rb + q * 16;
            b_off[q] = row * 64 + ((bkh ^ (row & 3)) * 16);
        }
    }

    float acc[2][4][4];
#pragma unroll
    for (int i = 0; i < 2; i++)
#pragma unroll
        for (int f = 0; f < 4; f++)
#pragma unroll
            for (int v = 0; v < 4; v++) acc[i][f][v] = 0.0f;

    // ---- prologue: issue chunks 0 and 1 ----
#pragma unroll
    for (int c = 0; c < 2; c++) {
        const uint32_t bo = c * BUFSZ;
        const uint32_t ko = c * KCH;
        cpa16(dA0 + bo + AH_OFF, hin_hi + sA0 + ko);
        cpa16(dA1 + bo + AH_OFF, hin_hi + sA1 + ko);
        cpa16(dA0 + bo + AL_OFF, hin_lo + sA0 + ko);
        cpa16(dA1 + bo + AL_OFF, hin_lo + sA1 + ko);
        cpa16(dB + bo + BH_OFF, wb_hi + sB + ko);
        cpa16(dB + bo + BL_OFF, wb_lo + sB + ko);
        CPA_COMMIT();
    }
    CPA_WAIT1();
    __syncthreads();

    int buf = 0;
    for (int c = 0; c < 16; c++) {
        if (c <= 13) {
            const uint32_t bo = ((c + 2) % NBUF) * BUFSZ;
            const uint32_t ko = (c + 2) * KCH;
            cpa16(dA0 + bo + AH_OFF, hin_hi + sA0 + ko);
            cpa16(dA1 + bo + AH_OFF, hin_hi + sA1 + ko);
            cpa16(dA0 + bo + AL_OFF, hin_lo + sA0 + ko);
            cpa16(dA1 + bo + AL_OFF, hin_lo + sA1 + ko);
            cpa16(dB + bo + BH_OFF, wb_hi + sB + ko);
            cpa16(dB + bo + BL_OFF, wb_lo + sB + ko);
            CPA_COMMIT();
        }

        const uint32_t base = smem_base + buf * BUFSZ;
#pragma unroll
        for (int s = 0; s < 2; s++) {
            const uint32_t sx = s ? 32u : 0u;
            uint32_t ah[2][4], al[2][4], bh[2][4], bl[2][4];
            // load all fragments up front (8 ldsm), then 24 independent mma
#pragma unroll
            for (int i = 0; i < 2; i++) ldsm_x4(ah[i], base + AH_OFF + (a_off[i] ^ sx));
#pragma unroll
            for (int q = 0; q < 2; q++) ldsm_x4(bh[q], base + BH_OFF + (b_off[q] ^ sx));
#pragma unroll
            for (int i = 0; i < 2; i++) ldsm_x4(al[i], base + AL_OFF + (a_off[i] ^ sx));
#pragma unroll
            for (int q = 0; q < 2; q++) ldsm_x4(bl[q], base + BL_OFF + (b_off[q] ^ sx));
            // pass hh
#pragma unroll
            for (int i = 0; i < 2; i++)
#pragma unroll
                for (int f = 0; f < 4; f++)
                    mma16816(acc[i][f], ah[i], &bh[f >> 1][(f & 1) * 2]);
            // pass hl (A hi x B lo)
#pragma unroll
            for (int i = 0; i < 2; i++)
#pragma unroll
                for (int f = 0; f < 4; f++)
                    mma16816(acc[i][f], ah[i], &bl[f >> 1][(f & 1) * 2]);
            // pass lh (A lo x B hi)
#pragma unroll
            for (int i = 0; i < 2; i++)
#pragma unroll
                for (int f = 0; f < 4; f++)
                    mma16816(acc[i][f], al[i], &bh[f >> 1][(f & 1) * 2]);
        }

        if (c <= 13) {
            CPA_WAIT1();
            __syncthreads();
        } else if (c == 14) {
            CPA_WAIT0();
            __syncthreads();
        }
        buf = (buf + 1 == NBUF) ? 0 : buf + 1;
    }

    // ---- stage accumulators to smem (overwrites dead operand buffers) ----
    __syncthreads();
    {
        const int rr = warp_m * 32 + (lid >> 2);
        const int c0 = warp_n * 32 + (lid & 3) * 2;
#pragma unroll
        for (int i = 0; i < 2; i++)
#pragma unroll
            for (int f = 0; f < 4; f++) {
                int r = rr + i * 16;
                int cc = c0 + f * 8;
                *(float2*)&E[r * EPI_STRIDE + cc]       = make_float2(acc[i][f][0], acc[i][f][1]);
                *(float2*)&E[(r + 8) * EPI_STRIDE + cc] = make_float2(acc[i][f][2], acc[i][f][3]);
            }
    }
    __syncthreads();

    // ---- fused LSTM cell epilogue (16 hcols x 128 rows) ----
    {
        const int hl = tid & 15;
        const int mb = (tid >> 4) * 8;
        const int hcol_g = by * 16 + hl;
#pragma unroll 4
        for (int j = 0; j < 8; j++) {
            const int m = mb + j;
            const int b = bm * 128 + m;
            const float* xg = g_xg + (size_t)b * GDIM + hcol_g;
            float gi = E[m * EPI_STRIDE + hl]      + xg[0];
            float gf = E[m * EPI_STRIDE + 16 + hl] + xg[512];
            float gg = E[m * EPI_STRIDE + 32 + hl] + xg[1024];
            float go = E[m * EPI_STRIDE + 48 + hl] + xg[1536];
            const size_t ci = (size_t)b * HDIM + hcol_g;
            float cn = sigm(gf) * g_c[ci] + sigm(gi) * tanh_fast(gg);
            g_c[ci] = cn;
            float hn = sigm(go) * tanh_fast(cn);
            g_hs[((size_t)b * TSTEP + t) * HDIM + hcol_g] = hn;
            __nv_bfloat16 hb = __float2bfloat16_rn(hn);
            float rem = hn - __bfloat162float(hb);
            hout_hi[ci] = hb;
            hout_lo[ci] = __float2bfloat16_rn(rem);
        }
    }
}

// -------- fc: out = relu(hs @ fc_w.T + fc_b) --------------------------------
__global__ __launch_bounds__(256)
void fc_kernel(const float* __restrict__ fc_w,
               const float* __restrict__ fc_b,
               float* __restrict__ out) {
    __shared__ float hsS[16][514];
    const size_t row0 = (size_t)blockIdx.x * 16;
    const int tid = threadIdx.x;

#pragma unroll
    for (int it = 0; it < 16; it++) {
        int i = tid + it * 256;
        int row = i >> 8;
        int cc = (i & 255) * 2;
        float2 v = *(const float2*)(g_hs + (row0 + row) * HDIM + cc);
        *(float2*)&hsS[row][cc] = v;
    }
    __syncthreads();

    const int r = tid & 15;
    const int v0 = (tid >> 4) * 4;
    ull acc[4] = {0ull, 0ull, 0ull, 0ull};
    const float* w0 = fc_w + (size_t)v0 * HDIM;

#pragma unroll 8
    for (int k = 0; k < HDIM; k += 2) {
        ull a = *(const ull*)&hsS[r][k];
        acc[0] = ffma2(a, *(const ull*)(w0 + k),        acc[0]);
        acc[1] = ffma2(a, *(const ull*)(w0 + 512 + k),  acc[1]);
        acc[2] = ffma2(a, *(const ull*)(w0 + 1024 + k), acc[2]);
        acc[3] = ffma2(a, *(const ull*)(w0 + 1536 + k), acc[3]);
    }
#pragma unroll
    for (int j = 0; j < 4; j++) {
        float2 s = up2(acc[j]);
        float v = s.x + s.y + fc_b[v0 + j];
        out[(row0 + r) * VDIM + v0 + j] = fmaxf(v, 0.0f);
    }
}

// ---------------- launch ----------------------------------------------------
extern "C" void kernel_launch(void* const* d_in, const int* in_sizes, int n_in,
                              void* d_out, int out_size) {
    const float* z    = (const float*)d_in[0];
    const float* w_ih = (const float*)d_in[1];
    const float* w_hh = (const float*)d_in[2];
    const float* b_ih = (const float*)d_in[3];
    const float* b_hh = (const float*)d_in[4];
    const float* fc_w = (const float*)d_in[5];
    const float* fc_b = (const float*)d_in[6];
    float* out = (float*)d_out;

    cudaFuncSetAttribute(step_mma, cudaFuncAttributeMaxDynamicSharedMemorySize, SMEM_TOTAL);

    init_kernel<<<(BATCH * HDIM + 255) / 256, 256>>>();
    wprep_kernel<<<(32 * 64 * HDIM + 255) / 256, 256>>>(w_hh);
    pre_kernel<<<dim3(16, 16), 256>>>(z, w_ih, b_ih, b_hh);
    for (int t = 0; t < TSTEP; t++) {
        step_mma<<<dim3(16, 32), 256, SMEM_TOTAL>>>(t);
    }
    fc_kernel<<<(BATCH * TSTEP) / 16, 256>>>(fc_w, fc_b, out);
}

// round 9
// speedup vs baseline: 3.4854x; 1.9555x over previous
#include <cuda_runtime.h>
#include <cuda_bf16.h>
#include <cuda_fp16.h>
#include <cstdint>
#include <math.h>

// Problem dims
#define BATCH 2048
#define HDIM  512
#define TSTEP 128
#define VDIM  64
#define GDIM  2048   // 4*HDIM

// ---------------- scratch (device globals; no allocation allowed) ----------
__device__ float g_xg[BATCH * GDIM];                         // 16 MB  x_gates
__device__ float g_c[BATCH * HDIM];                          // 4 MB   cell state
__device__ float g_hs[(size_t)BATCH * TSTEP * HDIM];         // 512 MB hidden states (fp32)
// h as fp16, double buffered by t parity
__device__ __half g_hA[2][BATCH * HDIM];
// w_hh fp16, rearranged per N-block (by in 0..15): [16][128 rows][512 k],
// tile row r -> orig row (r>>5)*512 + by*32 + (r&31)
__device__ __half g_wB[16][128 * HDIM];

// ---------------- packed f32x2 helpers (FFMA2 path) -------------------------
typedef unsigned long long ull;

__device__ __forceinline__ ull ffma2(ull a, ull b, ull c) {
    ull d;
    asm("fma.rn.f32x2 %0, %1, %2, %3;" : "=l"(d) : "l"(a), "l"(b), "l"(c));
    return d;
}
__device__ __forceinline__ ull pk2(float x, float y) {
    ull r;
    asm("mov.b64 %0, {%1, %2};" : "=l"(r) : "f"(x), "f"(y));
    return r;
}
__device__ __forceinline__ float2 up2(ull v) {
    float2 r;
    asm("mov.b64 {%0, %1}, %2;" : "=f"(r.x), "=f"(r.y) : "l"(v));
    return r;
}

__device__ __forceinline__ float sigm(float x) {
    return 1.0f / (1.0f + __expf(-x));
}
__device__ __forceinline__ float tanh_fast(float x) {
    float e = __expf(-2.0f * fabsf(x));
    float r = (1.0f - e) / (1.0f + e);
    return copysignf(r, x);
}

// ---------------- mma.sync / ldmatrix / cp.async helpers --------------------
__device__ __forceinline__ uint32_t smem_u32(const void* p) {
    uint32_t a;
    asm("{ .reg .u64 t; cvta.to.shared.u64 t, %1; cvt.u32.u64 %0, t; }" : "=r"(a) : "l"(p));
    return a;
}
__device__ __forceinline__ void ldsm_x4(uint32_t* r, uint32_t addr) {
    asm volatile("ldmatrix.sync.aligned.m8n8.x4.shared.b16 {%0,%1,%2,%3}, [%4];"
                 : "=r"(r[0]), "=r"(r[1]), "=r"(r[2]), "=r"(r[3]) : "r"(addr));
}
// fp16 MMA m16n8k16, f32 accum
__device__ __forceinline__ void mma16816h(float* d, const uint32_t* a, const uint32_t* b) {
    asm volatile("mma.sync.aligned.m16n8k16.row.col.f32.f16.f16.f32 "
                 "{%0,%1,%2,%3}, {%4,%5,%6,%7}, {%8,%9}, {%0,%1,%2,%3};"
                 : "+f"(d[0]), "+f"(d[1]), "+f"(d[2]), "+f"(d[3])
                 : "r"(a[0]), "r"(a[1]), "r"(a[2]), "r"(a[3]), "r"(b[0]), "r"(b[1]));
}
__device__ __forceinline__ void cpa16(uint32_t dst, const void* src) {
    asm volatile("cp.async.cg.shared.global [%0], [%1], 16;"
                 :: "r"(dst), "l"(__cvta_generic_to_global(src)) : "memory");
}
#define CPA_COMMIT() asm volatile("cp.async.commit_group;" ::: "memory")
#define CPA_WAIT0()  asm volatile("cp.async.wait_group 0;" ::: "memory")
#define CPA_WAIT1()  asm volatile("cp.async.wait_group 1;" ::: "memory")

// ---------------- init: zero c and h0 ----------------------------------------
__global__ void init_kernel() {
    int i = blockIdx.x * blockDim.x + threadIdx.x;
    if (i < BATCH * HDIM) {
        g_c[i] = 0.0f;
        g_hA[0][i] = __float2half(0.0f);
    }
}

// ---------------- wprep: fp16 convert + rearrange w_hh -----------------------
__global__ void wprep_kernel(const float* __restrict__ w_hh) {
    int i = blockIdx.x * blockDim.x + threadIdx.x;   // over 16*128*512
    if (i >= 16 * 128 * HDIM) return;
    int k = i & (HDIM - 1);
    int r = (i >> 9) & 127;
    int by = i >> 16;
    int orig_row = ((r >> 5) << 9) + by * 32 + (r & 31);
    g_wB[by][r * HDIM + k] = __float2half_rn(w_hh[(size_t)orig_row * HDIM + k]);
}

// -------- pre: x_gates = z @ w_ih.T + b_ih + b_hh (FFMA2, one-time) ----------
__global__ __launch_bounds__(256, 2)
void pre_kernel(const float* __restrict__ z,
                const float* __restrict__ w_ih,
                const float* __restrict__ b_ih,
                const float* __restrict__ b_hh) {
    __shared__ float As[16][132];
    __shared__ float Bs[16][130];

    const int bm = blockIdx.x;
    const int j0 = blockIdx.y * 32;
    const int tid = threadIdx.x;
    const int tr = tid >> 4, tc = tid & 15;
    const int jj0 = tc * 2;

    ull acc[8][4];
#pragma unroll
    for (int i = 0; i < 8; i++)
#pragma unroll
        for (int g = 0; g < 4; g++) acc[i][g] = 0ull;

    for (int k0 = 0; k0 < HDIM; k0 += 16) {
#pragma unroll
        for (int it = 0; it < 2; it++) {
            int i = tid + it * 256;
            int row = i >> 2, kq = (i & 3) * 4;
            float4 va = *(const float4*)(z + (size_t)(bm * 128 + row) * HDIM + k0 + kq);
            As[kq + 0][row] = va.x; As[kq + 1][row] = va.y;
            As[kq + 2][row] = va.z; As[kq + 3][row] = va.w;
            int n = row;
            int gcol = ((n >> 5) << 9) + j0 + (n & 31);
            float4 vb = *(const float4*)(w_ih + (size_t)gcol * HDIM + k0 + kq);
            Bs[kq + 0][n] = vb.x; Bs[kq + 1][n] = vb.y;
            Bs[kq + 2][n] = vb.z; Bs[kq + 3][n] = vb.w;
        }
        __syncthreads();
#pragma unroll
        for (int kk = 0; kk < 16; kk++) {
            float4 a0 = *(const float4*)&As[kk][tr * 8];
            float4 a1 = *(const float4*)&As[kk][tr * 8 + 4];
            ull b0 = *(const ull*)&Bs[kk][jj0];
            ull b1 = *(const ull*)&Bs[kk][32 + jj0];
            ull b2 = *(const ull*)&Bs[kk][64 + jj0];
            ull b3 = *(const ull*)&Bs[kk][96 + jj0];
            float av[8] = {a0.x, a0.y, a0.z, a0.w, a1.x, a1.y, a1.z, a1.w};
#pragma unroll
            for (int i = 0; i < 8; i++) {
                ull ad = pk2(av[i], av[i]);
                acc[i][0] = ffma2(ad, b0, acc[i][0]);
                acc[i][1] = ffma2(ad, b1, acc[i][1]);
                acc[i][2] = ffma2(ad, b2, acc[i][2]);
                acc[i][3] = ffma2(ad, b3, acc[i][3]);
            }
        }
        __syncthreads();
    }

    const int b0r = bm * 128 + tr * 8;
#pragma unroll
    for (int i = 0; i < 8; i++) {
        int b = b0r + i;
        float2 vv[4];
#pragma unroll
        for (int g = 0; g < 4; g++) vv[g] = up2(acc[i][g]);
#pragma unroll
        for (int g = 0; g < 4; g++) {
            int c0 = g * 512 + j0 + jj0;
            g_xg[(size_t)b * GDIM + c0]     = vv[g].x + b_ih[c0]     + b_hh[c0];
            g_xg[(size_t)b * GDIM + c0 + 1] = vv[g].y + b_ih[c0 + 1] + b_hh[c0 + 1];
        }
    }
}

// ============================================================================
// step_mma: gates = x_gates + h@w_hh.T via fp16 mma.sync SINGLE pass
//   grid (16, 16), 256 threads (8 warps), 2 CTAs/SM, single wave.
//   CTA tile M=128 x N=128 (n = g*32 + hcol), warp tile M64 x N32.
//   K=512 in 8 chunks of 64 elems (128B rows, full 8-unit swizzle),
//   cp.async triple buffer + register-level fragment double buffering.
// ============================================================================
#define KCH 64
#define B_OFF 16384
#define BUFSZ 32768
#define NBUF  3
#define EPI_STRIDE 132
#define SMEM_TOTAL (NBUF * BUFSZ)   // 98304 >= epi 128*132*4 = 67584

__global__ __launch_bounds__(256, 2)
void step_mma(int t) {
    extern __shared__ char smem[];
    const uint32_t smem_base = smem_u32(smem);
    float* E = (float*)smem;

    const int tid = threadIdx.x;
    const int wid = tid >> 5;
    const int lid = tid & 31;
    const int bm = blockIdx.x;
    const int by = blockIdx.y;

    const __half* __restrict__ hin = g_hA[t & 1];
    __half* __restrict__ hout = g_hA[(t & 1) ^ 1];
    const __half* __restrict__ wb = g_wB[by];

    // ---- ldmatrix lane address components ----
    const int warp_m = wid >> 2;           // 0..1 -> m base warp_m*64
    const int warp_n = wid & 3;            // 0..3 -> n base warp_n*32
    const int j = lid >> 3;
    const int kha = j >> 1;                // A k-half select
    const int khb = j & 1;                 // B k-half select
    uint32_t aB[4]; int a7[4];
    uint32_t bB[2]; int b7[2];
    {
        int ra = warp_m * 64 + (lid & 7) + ((j & 1) << 3);
#pragma unroll
        for (int i = 0; i < 4; i++) {
            int row = ra + i * 16;
            aB[i] = row * 128; a7[i] = row & 7;
        }
        int rb = warp_n * 32 + (lid & 7) + (((lid >> 4) & 1) << 3);
#pragma unroll
        for (int q = 0; q < 2; q++) {
            int row = rb + q * 16;
            bB[q] = row * 128; b7[q] = row & 7;
        }
    }

    // fragment double buffer + accumulators
    uint32_t af[2][4][4], bf[2][2][4];
    float acc[4][4][4];
#pragma unroll
    for (int i = 0; i < 4; i++)
#pragma unroll
        for (int f = 0; f < 4; f++)
#pragma unroll
            for (int v = 0; v < 4; v++) acc[i][f][v] = 0.0f;

#define ISSUE_CP(CH, BI) do {                                                   \
    const uint32_t _bo = (BI) * BUFSZ;                                          \
    const uint32_t _ko = (CH) * KCH;                                            \
    _Pragma("unroll")                                                           \
    for (int _it = 0; _it < 4; _it++) {                                         \
        int _q = tid + _it * 256;                                               \
        int _r = _q >> 3, _u = _q & 7;                                          \
        uint32_t _dst = smem_base + _bo + _r * 128 + (((_u ^ (_r & 7))) << 4);  \
        cpa16(_dst, hin + (uint32_t)(bm * 128 + _r) * HDIM + _ko + _u * 8);     \
        cpa16(_dst + B_OFF, wb + (uint32_t)_r * HDIM + _ko + _u * 8);           \
    }                                                                           \
} while (0)

#define LOADF(P, BASE, S) do {                                                  \
    const uint32_t _ua = 2 * (S) + kha;                                         \
    const uint32_t _ub = 2 * (S) + khb;                                         \
    _Pragma("unroll")                                                           \
    for (int _i = 0; _i < 4; _i++)                                              \
        ldsm_x4(af[P][_i], (BASE) + aB[_i] + ((_ua ^ a7[_i]) << 4));            \
    _Pragma("unroll")                                                           \
    for (int _q = 0; _q < 2; _q++)                                              \
        ldsm_x4(bf[P][_q], (BASE) + B_OFF + bB[_q] + ((_ub ^ b7[_q]) << 4));    \
} while (0)

#define MMA16(P) do {                                                           \
    _Pragma("unroll")                                                           \
    for (int _i = 0; _i < 4; _i++)                                              \
        _Pragma("unroll")                                                       \
        for (int _f = 0; _f < 4; _f++)                                          \
            mma16816h(acc[_i][_f], af[P][_i], &bf[P][_f >> 1][(_f & 1) * 2]);   \
} while (0)

    // ---- prologue: issue chunks 0 and 1 ----
    ISSUE_CP(0, 0); CPA_COMMIT();
    ISSUE_CP(1, 1); CPA_COMMIT();
    CPA_WAIT1();
    __syncthreads();
    LOADF(0, smem_base, 0);

    int buf = 0;
    for (int c = 0; c < 8; c++) {
        if (c <= 5) { ISSUE_CP(c + 2, (c + 2) % NBUF); CPA_COMMIT(); }
        const uint32_t base = smem_base + buf * BUFSZ;
        // s = 0
        LOADF(1, base, 1);
        MMA16(0);
        // s = 1
        LOADF(0, base, 2);
        MMA16(1);
        // s = 2
        LOADF(1, base, 3);
        MMA16(0);
        // s = 3
        MMA16(1);

        if (c <= 5) { CPA_WAIT1(); __syncthreads(); }
        else if (c == 6) { CPA_WAIT0(); __syncthreads(); }
        buf = (buf + 1 == NBUF) ? 0 : buf + 1;
        if (c < 7) LOADF(0, smem_base + buf * BUFSZ, 0);
    }

    // ---- stage accumulators to smem (overwrites dead operand buffers) ----
    __syncthreads();
    {
        const int rr = warp_m * 64 + (lid >> 2);
        const int c0 = warp_n * 32 + (lid & 3) * 2;
#pragma unroll
        for (int i = 0; i < 4; i++)
#pragma unroll
            for (int f = 0; f < 4; f++) {
                int r = rr + i * 16;
                int cc = c0 + f * 8;
                *(float2*)&E[r * EPI_STRIDE + cc]       = make_float2(acc[i][f][0], acc[i][f][1]);
                *(float2*)&E[(r + 8) * EPI_STRIDE + cc] = make_float2(acc[i][f][2], acc[i][f][3]);
            }
    }
    __syncthreads();

    // ---- fused LSTM cell epilogue (32 hcols x 128 rows) ----
    {
        const int hl = tid & 31;
        const int mb = (tid >> 5) * 16;
        const int hcol_g = by * 32 + hl;
#pragma unroll 4
        for (int jj = 0; jj < 16; jj++) {
            const int m = mb + jj;
            const int b = bm * 128 + m;
            const float* xg = g_xg + (size_t)b * GDIM + hcol_g;
            float gi = E[m * EPI_STRIDE + hl]      + xg[0];
            float gf = E[m * EPI_STRIDE + 32 + hl] + xg[512];
            float gg = E[m * EPI_STRIDE + 64 + hl] + xg[1024];
            float go = E[m * EPI_STRIDE + 96 + hl] + xg[1536];
            const size_t ci = (size_t)b * HDIM + hcol_g;
            float cn = sigm(gf) * g_c[ci] + sigm(gi) * tanh_fast(gg);
            g_c[ci] = cn;
            float hn = sigm(go) * tanh_fast(cn);
            g_hs[((size_t)b * TSTEP + t) * HDIM + hcol_g] = hn;
            hout[ci] = __float2half_rn(hn);
        }
    }
#undef ISSUE_CP
#undef LOADF
#undef MMA16
}

// -------- fc: out = relu(hs @ fc_w.T + fc_b) --------------------------------
__global__ __launch_bounds__(256)
void fc_kernel(const float* __restrict__ fc_w,
               const float* __restrict__ fc_b,
               float* __restrict__ out) {
    __shared__ float hsS[16][514];
    const size_t row0 = (size_t)blockIdx.x * 16;
    const int tid = threadIdx.x;

#pragma unroll
    for (int it = 0; it < 16; it++) {
        int i = tid + it * 256;
        int row = i >> 8;
        int cc = (i & 255) * 2;
        float2 v = *(const float2*)(g_hs + (row0 + row) * HDIM + cc);
        *(float2*)&hsS[row][cc] = v;
    }
    __syncthreads();

    const int r = tid & 15;
    const int v0 = (tid >> 4) * 4;
    ull acc[4] = {0ull, 0ull, 0ull, 0ull};
    const float* w0 = fc_w + (size_t)v0 * HDIM;

#pragma unroll 8
    for (int k = 0; k < HDIM; k += 2) {
        ull a = *(const ull*)&hsS[r][k];
        acc[0] = ffma2(a, *(const ull*)(w0 + k),        acc[0]);
        acc[1] = ffma2(a, *(const ull*)(w0 + 512 + k),  acc[1]);
        acc[2] = ffma2(a, *(const ull*)(w0 + 1024 + k), acc[2]);
        acc[3] = ffma2(a, *(const ull*)(w0 + 1536 + k), acc[3]);
    }
#pragma unroll
    for (int jj = 0; jj < 4; jj++) {
        float2 s = up2(acc[jj]);
        float v = s.x + s.y + fc_b[v0 + jj];
        out[(row0 + r) * VDIM + v0 + jj] = fmaxf(v, 0.0f);
    }
}

// ---------------- launch ----------------------------------------------------
extern "C" void kernel_launch(void* const* d_in, const int* in_sizes, int n_in,
                              void* d_out, int out_size) {
    const float* z    = (const float*)d_in[0];
    const float* w_ih = (const float*)d_in[1];
    const float* w_hh = (const float*)d_in[2];
    const float* b_ih = (const float*)d_in[3];
    const float* b_hh = (const float*)d_in[4];
    const float* fc_w = (const float*)d_in[5];
    const float* fc_b = (const float*)d_in[6];
    float* out = (float*)d_out;

    cudaFuncSetAttribute(step_mma, cudaFuncAttributeMaxDynamicSharedMemorySize, SMEM_TOTAL);

    init_kernel<<<(BATCH * HDIM + 255) / 256, 256>>>();
    wprep_kernel<<<(16 * 128 * HDIM + 255) / 256, 256>>>(w_hh);
    pre_kernel<<<dim3(16, 16), 256>>>(z, w_ih, b_ih, b_hh);
    for (int t = 0; t < TSTEP; t++) {
        step_mma<<<dim3(16, 16), 256, SMEM_TOTAL>>>(t);
    }
    fc_kernel<<<(BATCH * TSTEP) / 16, 256>>>(fc_w, fc_b, out);
}